// round 1
// baseline (speedup 1.0000x reference)
#include <cuda_runtime.h>

#define NB 2
#define NC 256
#define HW 2304   // 48*48
#define WD 48

// Scratch for q/k/v maps, [B][C][H][W] planes, fp32.
__device__ float g_q[NB * NC * HW];
__device__ float g_k[NB * NC * HW];
__device__ float g_v[NB * NC * HW];

// ---------------------------------------------------------------------------
// Projection GEMM: out[b,o,p] = sum_c x[b,c,p] * w[o,c]
// Tile: 128 pixels x 64 out-channels, K-tile 16. 256 threads, 4pix x 8oc micro.
// grid = (18, 4, 6)  [pixel tiles, oc tiles, b*3+which]
// ---------------------------------------------------------------------------
__global__ __launch_bounds__(256) void proj_kernel(
    const float* __restrict__ x,
    const float* __restrict__ wq,
    const float* __restrict__ wk,
    const float* __restrict__ wv)
{
    __shared__ float Xs[16][128];   // [kk][pix]
    __shared__ float Ws[16][68];    // [kk][oc], padded row (272B, 16B aligned)

    int z = blockIdx.z;
    int b = z / 3;
    int which = z - b * 3;
    const float* w   = (which == 0) ? wq : (which == 1) ? wk : wv;
    float*       obf = (which == 0) ? g_q : (which == 1) ? g_k : g_v;

    const float* xb = x   + b * NC * HW;
    float*       ob = obf + b * NC * HW;

    int p0 = blockIdx.x * 128;
    int o0 = blockIdx.y * 64;
    int tid = threadIdx.x;
    int tx = tid & 31;       // pixel group (4 pixels each)
    int ty = tid >> 5;       // oc group (8 oc each)

    float acc[8][4];
    #pragma unroll
    for (int j = 0; j < 8; j++) {
        acc[j][0] = 0.f; acc[j][1] = 0.f; acc[j][2] = 0.f; acc[j][3] = 0.f;
    }

    for (int kc = 0; kc < 256; kc += 16) {
        // Load X tile: 16 rows x 128 pix = 512 float4-loads across 256 threads.
        #pragma unroll
        for (int i = 0; i < 2; i++) {
            int t   = tid + i * 256;
            int row = t >> 5;
            int c4  = (t & 31) << 2;
            float4 v4 = *(const float4*)(xb + (kc + row) * HW + p0 + c4);
            *(float4*)(&Xs[row][c4]) = v4;
        }
        // Load W tile (transposed into smem): 64 oc x 16 kk.
        {
            int oc = tid >> 2;
            int kg = (tid & 3) << 2;
            float4 v4 = *(const float4*)(w + (o0 + oc) * 256 + kc + kg);
            Ws[kg + 0][oc] = v4.x;
            Ws[kg + 1][oc] = v4.y;
            Ws[kg + 2][oc] = v4.z;
            Ws[kg + 3][oc] = v4.w;
        }
        __syncthreads();

        #pragma unroll
        for (int kk = 0; kk < 16; kk++) {
            float4 xv = *(const float4*)(&Xs[kk][tx << 2]);
            float4 w0 = *(const float4*)(&Ws[kk][ty * 8]);
            float4 w1 = *(const float4*)(&Ws[kk][ty * 8 + 4]);
            float wr[8] = {w0.x, w0.y, w0.z, w0.w, w1.x, w1.y, w1.z, w1.w};
            #pragma unroll
            for (int j = 0; j < 8; j++) {
                acc[j][0] = fmaf(wr[j], xv.x, acc[j][0]);
                acc[j][1] = fmaf(wr[j], xv.y, acc[j][1]);
                acc[j][2] = fmaf(wr[j], xv.z, acc[j][2]);
                acc[j][3] = fmaf(wr[j], xv.w, acc[j][3]);
            }
        }
        __syncthreads();
    }

    #pragma unroll
    for (int j = 0; j < 8; j++) {
        float4 r = make_float4(acc[j][0], acc[j][1], acc[j][2], acc[j][3]);
        *(float4*)(ob + (o0 + ty * 8 + j) * HW + p0 + (tx << 2)) = r;
    }
}

// ---------------------------------------------------------------------------
// Attention: one block per (b, c) plane. k/v plane staged in zero-padded
// 54x56 smem tile (col = x+4, row = y+3). Each thread computes 4 adjacent
// outputs -> window rows load as 3 aligned LDS.128 instead of 28 scalars.
// logit = q * (k + bias); padded taps contribute exp(q*bias) to the sum
// with v = 0, exactly matching the reference.
// Single-pass softmax (no max subtraction): |logit| <~ 25 here, safe in fp32.
// grid = 512 blocks, 256 threads.
// ---------------------------------------------------------------------------
__global__ __launch_bounds__(256) void attn_kernel(
    const float* __restrict__ rel_h,
    const float* __restrict__ rel_w,
    float* __restrict__ out)
{
    __shared__ float ks[54 * 56];
    __shared__ float vs[54 * 56];

    int plane = blockIdx.x;
    int c = plane & 255;
    const float* kp = g_k + plane * HW;
    const float* vp = g_v + plane * HW;
    const float* qp = g_q + plane * HW;
    float*       op = out + plane * HW;

    int tid = threadIdx.x;

    for (int i = tid; i < 54 * 56; i += 256) { ks[i] = 0.f; vs[i] = 0.f; }
    __syncthreads();
    for (int i = tid; i < HW; i += 256) {
        int y  = i / WD;
        int xx = i - y * WD;
        int s  = (y + 3) * 56 + (xx + 4);
        ks[s] = kp[i];
        vs[s] = vp[i];
    }

    bool useH = (c < 128);
    const float* rb = useH ? (rel_h + c * 7) : (rel_w + (c - 128) * 7);
    float bias[7];
    #pragma unroll
    for (int j = 0; j < 7; j++) bias[j] = rb[j];
    __syncthreads();

    // 48 rows x 12 groups-of-4 = 576 groups
    for (int g = tid; g < 576; g += 256) {
        int row = g / 12;
        int w0  = (g - row * 12) << 2;

        float4 q4 = *(const float4*)(qp + row * WD + w0);
        float qv[4] = {q4.x, q4.y, q4.z, q4.w};
        float ssum[4] = {0.f, 0.f, 0.f, 0.f};
        float avec[4] = {0.f, 0.f, 0.f, 0.f};

        #pragma unroll
        for (int kh = 0; kh < 7; kh++) {
            const float* kr = &ks[(row + kh) * 56 + w0];
            const float* vr = &vs[(row + kh) * 56 + w0];
            float kvv[12], vvv[12];
            {
                float4 t0 = *(const float4*)(kr);
                float4 t1 = *(const float4*)(kr + 4);
                float4 t2 = *(const float4*)(kr + 8);
                kvv[0]=t0.x; kvv[1]=t0.y; kvv[2]=t0.z; kvv[3]=t0.w;
                kvv[4]=t1.x; kvv[5]=t1.y; kvv[6]=t1.z; kvv[7]=t1.w;
                kvv[8]=t2.x; kvv[9]=t2.y; kvv[10]=t2.z; kvv[11]=t2.w;
                float4 u0 = *(const float4*)(vr);
                float4 u1 = *(const float4*)(vr + 4);
                float4 u2 = *(const float4*)(vr + 8);
                vvv[0]=u0.x; vvv[1]=u0.y; vvv[2]=u0.z; vvv[3]=u0.w;
                vvv[4]=u1.x; vvv[5]=u1.y; vvv[6]=u1.z; vvv[7]=u1.w;
                vvv[8]=u2.x; vvv[9]=u2.y; vvv[10]=u2.z; vvv[11]=u2.w;
            }
            float bh = bias[kh];
            #pragma unroll
            for (int kw = 0; kw < 7; kw++) {
                float bb = useH ? bh : bias[kw];
                #pragma unroll
                for (int o = 0; o < 4; o++) {
                    int idx = o + kw + 1;   // window col (x' + 4) - w0
                    float e = __expf(qv[o] * (kvv[idx] + bb));
                    ssum[o] += e;
                    avec[o] = fmaf(e, vvv[idx], avec[o]);
                }
            }
        }

        float4 r = make_float4(avec[0] / ssum[0], avec[1] / ssum[1],
                               avec[2] / ssum[2], avec[3] / ssum[3]);
        *(float4*)(op + row * WD + w0) = r;
    }
}

extern "C" void kernel_launch(void* const* d_in, const int* in_sizes, int n_in,
                              void* d_out, int out_size) {
    const float* x  = (const float*)d_in[0];
    const float* wq = (const float*)d_in[1];
    const float* wk = (const float*)d_in[2];
    const float* wv = (const float*)d_in[3];
    const float* rh = (const float*)d_in[4];
    const float* rw = (const float*)d_in[5];

    dim3 g1(HW / 128, NC / 64, NB * 3);
    proj_kernel<<<g1, 256>>>(x, wq, wk, wv);
    attn_kernel<<<NB * NC, 256>>>(rh, rw, (float*)d_out);
}

// round 3
// speedup vs baseline: 1.0571x; 1.0571x over previous
#include <cuda_runtime.h>
#include <cuda_bf16.h>
#include <cstdint>

#define NB 2
#define NC 256
#define HW 2304   // 48*48
#define WD 48
#define NPIX (NB * HW)   // 4608

// ---------------- device scratch ----------------
__device__ float g_q[NB * NC * HW];
__device__ float g_k[NB * NC * HW];
__device__ float g_v[NB * NC * HW];
// x transposed to [pixel][channel], bf16 hi/lo split
__device__ __nv_bfloat16 g_xt_hi[NPIX * 256];
__device__ __nv_bfloat16 g_xt_lo[NPIX * 256];
// concat(wq,wk,wv) rows, [768][256] bf16 hi/lo
__device__ __nv_bfloat16 g_w_hi[768 * 256];
__device__ __nv_bfloat16 g_w_lo[768 * 256];

__device__ __forceinline__ uint32_t smem_u32(const void* p) {
    uint32_t a;
    asm("{ .reg .u64 t; cvta.to.shared.u64 t, %1; cvt.u32.u64 %0, t; }"
        : "=r"(a) : "l"(p));
    return a;
}

// ---------------------------------------------------------------------------
// prep_w: fp32 weights -> bf16 hi/lo split, rows = [wq; wk; wv]
// ---------------------------------------------------------------------------
__global__ void prep_w(const float* __restrict__ wq, const float* __restrict__ wk,
                       const float* __restrict__ wv) {
    int o = blockIdx.x;             // 0..767
    int c = threadIdx.x;            // 0..255
    const float* src = (o < 256) ? (wq + o * 256)
                      : (o < 512) ? (wk + (o - 256) * 256)
                                  : (wv + (o - 512) * 256);
    float v = src[c];
    __nv_bfloat16 hi = __float2bfloat16(v);
    float lo = v - __bfloat162float(hi);
    g_w_hi[o * 256 + c] = hi;
    g_w_lo[o * 256 + c] = __float2bfloat16(lo);
}

// ---------------------------------------------------------------------------
// prep_x: transpose x [b][c][p] -> Xt[P][c], bf16 hi/lo. grid (72,8,2), 32x32.
// ---------------------------------------------------------------------------
__global__ void prep_x(const float* __restrict__ x) {
    __shared__ float t[32][33];
    int tx = threadIdx.x, ty = threadIdx.y;
    int p0 = blockIdx.x * 32;
    int c0 = blockIdx.y * 32;
    int b  = blockIdx.z;
    t[ty][tx] = x[(b * 256 + c0 + ty) * HW + p0 + tx];
    __syncthreads();
    int P  = b * HW + p0 + ty;
    int cc = c0 + tx;
    float v = t[tx][ty];
    __nv_bfloat16 hi = __float2bfloat16(v);
    float lo = v - __bfloat162float(hi);
    g_xt_hi[P * 256 + cc] = hi;
    g_xt_lo[P * 256 + cc] = __float2bfloat16(lo);
}

// ---------------------------------------------------------------------------
// GEMM via mma.sync m16n8k16 bf16 (sm_100-legal HMMA path).
// D[oc, pix] = sum_c W[oc,c]*X[pix,c]; hi/lo split -> 3 accumulating passes
// over the SAME smem tiles. Block 128oc x 128pix, 8 warps (2x4), warp tile
// 64x32 (4x4 mma tiles). K-tile 64. Smem pitch 72 bf16 (conflict-free for
// ldmatrix and STS.128 fills).
// grid (36 pix-tiles, 6 oc-tiles), 256 threads.
// ---------------------------------------------------------------------------
#define TILE_B 18432              // 128 * 72 * 2 bytes
#define GEMM_SMEM (4 * TILE_B)    // Whi, Wlo, Xhi, Xlo

__device__ __forceinline__ void mma_bf16(float* d, const uint32_t* a,
                                         const uint32_t* b) {
    asm volatile(
        "mma.sync.aligned.m16n8k16.row.col.f32.bf16.bf16.f32 "
        "{%0,%1,%2,%3}, {%4,%5,%6,%7}, {%8,%9}, {%0,%1,%2,%3};"
        : "+f"(d[0]), "+f"(d[1]), "+f"(d[2]), "+f"(d[3])
        : "r"(a[0]), "r"(a[1]), "r"(a[2]), "r"(a[3]), "r"(b[0]), "r"(b[1]));
}

__global__ __launch_bounds__(256, 2) void gemm_kernel() {
    extern __shared__ char sm[];
    uint32_t uS = smem_u32(sm);

    int tid = threadIdx.x;
    int wid = tid >> 5;
    int l   = tid & 31;
    int wm  = wid >> 2;      // 0-1  (oc dir, 64 each)
    int wn  = wid & 3;       // 0-3  (pix dir, 32 each)

    int N0 = blockIdx.x * 128;     // global pixel base
    int M0 = blockIdx.y * 128;     // oc base

    const char* srcs[4] = {
        (const char*)g_w_hi  + (size_t)M0 * 512,
        (const char*)g_w_lo  + (size_t)M0 * 512,
        (const char*)g_xt_hi + (size_t)N0 * 512,
        (const char*)g_xt_lo + (size_t)N0 * 512,
    };

    float acc[4][4][4];
    #pragma unroll
    for (int i = 0; i < 4; i++)
        #pragma unroll
        for (int j = 0; j < 4; j++)
            #pragma unroll
            for (int r = 0; r < 4; r++) acc[i][j][r] = 0.f;

    // ldmatrix lane base addresses (byte offsets within a tile)
    uint32_t aLane = (uint32_t)((wm * 64 + (l & 15)) * 144 + (l >> 4) * 16);
    uint32_t bLane = (uint32_t)((wn * 32 + (l & 7)) * 144 + (((l & 15) >> 3) * 16));

    const int selA[3] = {0, 0, 1};   // hi*hi + hi*lo + lo*hi
    const int selB[3] = {0, 1, 0};

    for (int kt = 0; kt < 4; kt++) {
        __syncthreads();
        // fill 4 tiles: 4096 16B-chunks over 256 threads
        #pragma unroll
        for (int it = 0; it < 16; it++) {
            int lin  = it * 256 + tid;
            int tile = lin >> 10;
            int rem  = lin & 1023;
            int row  = rem >> 3;
            int ch   = rem & 7;
            uint4 v = *(const uint4*)(srcs[tile] + row * 512 + kt * 128 + ch * 16);
            *(uint4*)(sm + tile * TILE_B + row * 144 + ch * 16) = v;
        }
        __syncthreads();

        #pragma unroll
        for (int pp = 0; pp < 3; pp++) {
            uint32_t aBase = uS + selA[pp] * TILE_B + aLane;
            uint32_t bBase = uS + 2 * TILE_B + selB[pp] * TILE_B + bLane;
            #pragma unroll
            for (int ks = 0; ks < 4; ks++) {
                uint32_t af[4][4];
                uint32_t bf[4][2];
                #pragma unroll
                for (int i = 0; i < 4; i++) {
                    uint32_t ad = aBase + i * (16 * 144) + ks * 32;
                    asm volatile(
                        "ldmatrix.sync.aligned.m8n8.x4.shared.b16 "
                        "{%0,%1,%2,%3}, [%4];"
                        : "=r"(af[i][0]), "=r"(af[i][1]),
                          "=r"(af[i][2]), "=r"(af[i][3]) : "r"(ad));
                }
                #pragma unroll
                for (int j = 0; j < 4; j++) {
                    uint32_t bd = bBase + j * (8 * 144) + ks * 32;
                    asm volatile(
                        "ldmatrix.sync.aligned.m8n8.x2.shared.b16 "
                        "{%0,%1}, [%2];"
                        : "=r"(bf[j][0]), "=r"(bf[j][1]) : "r"(bd));
                }
                #pragma unroll
                for (int i = 0; i < 4; i++)
                    #pragma unroll
                    for (int j = 0; j < 4; j++)
                        mma_bf16(acc[i][j], af[i], bf[j]);
            }
        }
    }

    // Epilogue: D[oc][pix]; c0,c1 = consecutive pixels -> float2 stores.
    int b  = N0 / HW;
    int pl = N0 - b * HW;
    float* obuf = (M0 < 256) ? g_q : (M0 < 512) ? g_k : g_v;
    int ol = M0 & 255;
    int g  = l >> 2;
    int tc = l & 3;
    float* base = obuf + (size_t)b * NC * HW;

    #pragma unroll
    for (int i = 0; i < 4; i++) {
        int oc0 = ol + wm * 64 + i * 16 + g;
        #pragma unroll
        for (int j = 0; j < 4; j++) {
            int pix = pl + wn * 32 + j * 8 + tc * 2;
            *(float2*)(base + (size_t)oc0 * HW + pix) =
                make_float2(acc[i][j][0], acc[i][j][1]);
            *(float2*)(base + (size_t)(oc0 + 8) * HW + pix) =
                make_float2(acc[i][j][2], acc[i][j][3]);
        }
    }
}

// ---------------------------------------------------------------------------
// Attention: 192 threads, exactly 3 groups/thread. Per tap: FFMA + EX2 +
// FADD + FFMA. q' = q*log2e hoisted, q'*bias precomputed, bias mode templated.
// ---------------------------------------------------------------------------
template <bool USEH>
__global__ __launch_bounds__(192) void attn_kernel(
    const float* __restrict__ rel, float* __restrict__ out)
{
    __shared__ float kvbuf[2 * 3024];    // 54x56 k tile, then v tile
    float* ks = kvbuf;
    float* vs = kvbuf + 3024;

    int b  = blockIdx.x >> 7;
    int cl = blockIdx.x & 127;
    int c  = USEH ? cl : (128 + cl);
    int plane = b * 256 + c;

    const float* kp = g_k + (size_t)plane * HW;
    const float* vp = g_v + (size_t)plane * HW;
    const float* qp = g_q + (size_t)plane * HW;
    float*       op = out + (size_t)plane * HW;

    int tid = threadIdx.x;

    for (int i = tid; i < 1512; i += 192)
        ((float4*)kvbuf)[i] = make_float4(0.f, 0.f, 0.f, 0.f);
    __syncthreads();
    for (int i = tid; i < 576; i += 192) {
        int y  = i / 12;
        int x4 = (i - y * 12) << 2;
        int s  = (y + 3) * 56 + x4 + 4;
        *(float4*)(ks + s) = *(const float4*)(kp + y * WD + x4);
        *(float4*)(vs + s) = *(const float4*)(vp + y * WD + x4);
    }
    float bias[7];
    #pragma unroll
    for (int j = 0; j < 7; j++) bias[j] = rel[cl * 7 + j];
    __syncthreads();

    const float LOG2E = 1.4426950408889634f;
    #pragma unroll
    for (int it = 0; it < 3; it++) {
        int gg  = tid + it * 192;
        int row = gg / 12;
        int w0  = (gg - row * 12) << 2;

        float4 q4 = *(const float4*)(qp + row * WD + w0);
        float ql[4] = {q4.x * LOG2E, q4.y * LOG2E, q4.z * LOG2E, q4.w * LOG2E};
        float qb[4][7];
        #pragma unroll
        for (int o = 0; o < 4; o++)
            #pragma unroll
            for (int j = 0; j < 7; j++) qb[o][j] = ql[o] * bias[j];

        float ssum[4] = {0.f, 0.f, 0.f, 0.f};
        float avec[4] = {0.f, 0.f, 0.f, 0.f};

        #pragma unroll
        for (int kh = 0; kh < 7; kh++) {
            const float* kr = &ks[(row + kh) * 56 + w0];
            const float* vr = &vs[(row + kh) * 56 + w0];
            float kvv[12], vvv[12];
            {
                float4 t0 = *(const float4*)(kr);
                float4 t1 = *(const float4*)(kr + 4);
                float4 t2 = *(const float4*)(kr + 8);
                kvv[0]=t0.x; kvv[1]=t0.y; kvv[2]=t0.z; kvv[3]=t0.w;
                kvv[4]=t1.x; kvv[5]=t1.y; kvv[6]=t1.z; kvv[7]=t1.w;
                kvv[8]=t2.x; kvv[9]=t2.y; kvv[10]=t2.z; kvv[11]=t2.w;
                float4 u0 = *(const float4*)(vr);
                float4 u1 = *(const float4*)(vr + 4);
                float4 u2 = *(const float4*)(vr + 8);
                vvv[0]=u0.x; vvv[1]=u0.y; vvv[2]=u0.z; vvv[3]=u0.w;
                vvv[4]=u1.x; vvv[5]=u1.y; vvv[6]=u1.z; vvv[7]=u1.w;
                vvv[8]=u2.x; vvv[9]=u2.y; vvv[10]=u2.z; vvv[11]=u2.w;
            }
            #pragma unroll
            for (int kw = 0; kw < 7; kw++) {
                #pragma unroll
                for (int o = 0; o < 4; o++) {
                    int idx = o + kw + 1;
                    float qbb = USEH ? qb[o][kh] : qb[o][kw];
                    float t = fmaf(ql[o], kvv[idx], qbb);
                    float e;
                    asm("ex2.approx.f32 %0, %1;" : "=f"(e) : "f"(t));
                    ssum[o] += e;
                    avec[o] = fmaf(e, vvv[idx], avec[o]);
                }
            }
        }
        float4 r = make_float4(avec[0] / ssum[0], avec[1] / ssum[1],
                               avec[2] / ssum[2], avec[3] / ssum[3]);
        *(float4*)(op + row * WD + w0) = r;
    }
}

extern "C" void kernel_launch(void* const* d_in, const int* in_sizes, int n_in,
                              void* d_out, int out_size) {
    const float* x  = (const float*)d_in[0];
    const float* wq = (const float*)d_in[1];
    const float* wk = (const float*)d_in[2];
    const float* wv = (const float*)d_in[3];
    const float* rh = (const float*)d_in[4];
    const float* rw = (const float*)d_in[5];

    cudaFuncSetAttribute(gemm_kernel, cudaFuncAttributeMaxDynamicSharedMemorySize,
                         GEMM_SMEM);

    prep_w<<<768, 256>>>(wq, wk, wv);
    prep_x<<<dim3(72, 8, 2), dim3(32, 32)>>>(x);
    gemm_kernel<<<dim3(36, 6), 256, GEMM_SMEM>>>();
    attn_kernel<true><<<256, 192>>>(rh, (float*)d_out);
    attn_kernel<false><<<256, 192>>>(rw, (float*)d_out);
}

// round 4
// speedup vs baseline: 1.1362x; 1.0748x over previous
#include <cuda_runtime.h>
#include <cuda_bf16.h>
#include <cstdint>

#define NB 2
#define NC 256
#define HW 2304   // 48*48
#define WD 48
#define NPIX (NB * HW)   // 4608

// ---------------- device scratch ----------------
__device__ float g_q[NB * NC * HW];
__device__ float g_k[NB * NC * HW];
__device__ float g_v[NB * NC * HW];
__device__ __nv_bfloat16 g_xt_hi[NPIX * 256];
__device__ __nv_bfloat16 g_xt_lo[NPIX * 256];
__device__ __nv_bfloat16 g_w_hi[768 * 256];
__device__ __nv_bfloat16 g_w_lo[768 * 256];

__device__ __forceinline__ uint32_t smem_u32(const void* p) {
    uint32_t a;
    asm("{ .reg .u64 t; cvta.to.shared.u64 t, %1; cvt.u32.u64 %0, t; }"
        : "=r"(a) : "l"(p));
    return a;
}

// ---------------------------------------------------------------------------
// prep: merged. z<2: transpose x [b][c][p] -> Xt[P][c] bf16 hi/lo (32x32 tile).
//       z==2: weight rows [wq;wk;wv] -> bf16 hi/lo.
// grid (72, 8, 3), block (32,32) = 1024 thr.
// ---------------------------------------------------------------------------
__global__ void prep_kernel(const float* __restrict__ x,
                            const float* __restrict__ wq,
                            const float* __restrict__ wk,
                            const float* __restrict__ wv) {
    int tx = threadIdx.x, ty = threadIdx.y;
    if (blockIdx.z == 2) {
        // 576 blocks x 1024 threads cover 768*256 = 196608 elems
        int lin = (blockIdx.y * 72 + blockIdx.x) * 1024 + ty * 32 + tx;
        if (lin < 768 * 256) {
            int o = lin >> 8;
            int c = lin & 255;
            const float* src = (o < 256) ? (wq + o * 256)
                              : (o < 512) ? (wk + (o - 256) * 256)
                                          : (wv + (o - 512) * 256);
            float v = src[c];
            __nv_bfloat16 hi = __float2bfloat16(v);
            g_w_hi[lin] = hi;
            g_w_lo[lin] = __float2bfloat16(v - __bfloat162float(hi));
        }
        return;
    }
    __shared__ float t[32][33];
    int p0 = blockIdx.x * 32;
    int c0 = blockIdx.y * 32;
    int b  = blockIdx.z;
    t[ty][tx] = x[(b * 256 + c0 + ty) * HW + p0 + tx];
    __syncthreads();
    int P  = b * HW + p0 + ty;
    int cc = c0 + tx;
    float v = t[tx][ty];
    __nv_bfloat16 hi = __float2bfloat16(v);
    g_xt_hi[P * 256 + cc] = hi;
    g_xt_lo[P * 256 + cc] = __float2bfloat16(v - __bfloat162float(hi));
}

// ---------------------------------------------------------------------------
// GEMM via mma.sync m16n8k16 bf16. D[oc,pix] = W·Xt^T, hi/lo 3-pass split.
// Block 128oc x 128pix, 8 warps (2x4), warp 64x32, K-tile 64, pitch 72 bf16.
// grid (36, 6), 256 threads.
// ---------------------------------------------------------------------------
#define TILE_B 18432
#define GEMM_SMEM (4 * TILE_B)

__device__ __forceinline__ void mma_bf16(float* d, const uint32_t* a,
                                         const uint32_t* b) {
    asm volatile(
        "mma.sync.aligned.m16n8k16.row.col.f32.bf16.bf16.f32 "
        "{%0,%1,%2,%3}, {%4,%5,%6,%7}, {%8,%9}, {%0,%1,%2,%3};"
        : "+f"(d[0]), "+f"(d[1]), "+f"(d[2]), "+f"(d[3])
        : "r"(a[0]), "r"(a[1]), "r"(a[2]), "r"(a[3]), "r"(b[0]), "r"(b[1]));
}

__global__ __launch_bounds__(256, 2) void gemm_kernel() {
    extern __shared__ char sm[];
    uint32_t uS = smem_u32(sm);

    int tid = threadIdx.x;
    int l   = tid & 31;
    int wid = tid >> 5;
    int wm  = wid >> 2;
    int wn  = wid & 3;

    int N0 = blockIdx.x * 128;
    int M0 = blockIdx.y * 128;

    const char* srcs[4] = {
        (const char*)g_w_hi  + (size_t)M0 * 512,
        (const char*)g_w_lo  + (size_t)M0 * 512,
        (const char*)g_xt_hi + (size_t)N0 * 512,
        (const char*)g_xt_lo + (size_t)N0 * 512,
    };

    float acc[4][4][4];
    #pragma unroll
    for (int i = 0; i < 4; i++)
        #pragma unroll
        for (int j = 0; j < 4; j++)
            #pragma unroll
            for (int r = 0; r < 4; r++) acc[i][j][r] = 0.f;

    uint32_t aLane = (uint32_t)((wm * 64 + (l & 15)) * 144 + (l >> 4) * 16);
    uint32_t bLane = (uint32_t)((wn * 32 + (l & 7)) * 144 + (((l & 15) >> 3) * 16));

    const int selA[3] = {0, 0, 1};
    const int selB[3] = {0, 1, 0};

    for (int kt = 0; kt < 4; kt++) {
        __syncthreads();
        #pragma unroll
        for (int it = 0; it < 16; it++) {
            int lin  = it * 256 + tid;
            int tile = lin >> 10;
            int rem  = lin & 1023;
            int row  = rem >> 3;
            int ch   = rem & 7;
            uint4 v = *(const uint4*)(srcs[tile] + row * 512 + kt * 128 + ch * 16);
            *(uint4*)(sm + tile * TILE_B + row * 144 + ch * 16) = v;
        }
        __syncthreads();

        #pragma unroll
        for (int pp = 0; pp < 3; pp++) {
            uint32_t aBase = uS + selA[pp] * TILE_B + aLane;
            uint32_t bBase = uS + 2 * TILE_B + selB[pp] * TILE_B + bLane;
            #pragma unroll
            for (int ks = 0; ks < 4; ks++) {
                uint32_t af[4][4];
                uint32_t bf[4][2];
                #pragma unroll
                for (int i = 0; i < 4; i++) {
                    uint32_t ad = aBase + i * (16 * 144) + ks * 32;
                    asm volatile(
                        "ldmatrix.sync.aligned.m8n8.x4.shared.b16 "
                        "{%0,%1,%2,%3}, [%4];"
                        : "=r"(af[i][0]), "=r"(af[i][1]),
                          "=r"(af[i][2]), "=r"(af[i][3]) : "r"(ad));
                }
                #pragma unroll
                for (int j = 0; j < 4; j++) {
                    uint32_t bd = bBase + j * (8 * 144) + ks * 32;
                    asm volatile(
                        "ldmatrix.sync.aligned.m8n8.x2.shared.b16 "
                        "{%0,%1}, [%2];"
                        : "=r"(bf[j][0]), "=r"(bf[j][1]) : "r"(bd));
                }
                #pragma unroll
                for (int i = 0; i < 4; i++)
                    #pragma unroll
                    for (int j = 0; j < 4; j++)
                        mma_bf16(acc[i][j], af[i], bf[j]);
            }
        }
    }

    int b  = N0 / HW;
    int pl = N0 - b * HW;
    float* obuf = (M0 < 256) ? g_q : (M0 < 512) ? g_k : g_v;
    int ol = M0 & 255;
    int g  = l >> 2;
    int tc = l & 3;
    float* base = obuf + (size_t)b * NC * HW;

    #pragma unroll
    for (int i = 0; i < 4; i++) {
        int oc0 = ol + wm * 64 + i * 16 + g;
        #pragma unroll
        for (int j = 0; j < 4; j++) {
            int pix = pl + wn * 32 + j * 8 + tc * 2;
            *(float2*)(base + (size_t)oc0 * HW + pix) =
                make_float2(acc[i][j][0], acc[i][j][1]);
            *(float2*)(base + (size_t)(oc0 + 8) * HW + pix) =
                make_float2(acc[i][j][2], acc[i][j][3]);
        }
    }
}

// ---------------------------------------------------------------------------
// Attention: ONE launch, 512 blocks x 192 threads (~21 warps/SM -> MUFU
// saturation). Block-uniform branch selects bias mode; per-tap:
// FFMA + EX2 + FADD + FFMA.
// ---------------------------------------------------------------------------
template <bool USEH>
__device__ __forceinline__ void attn_compute(
    const float* __restrict__ ks, const float* __restrict__ vs,
    const float* __restrict__ qp, float* __restrict__ op,
    const float* bias, int tid)
{
    const float LOG2E = 1.4426950408889634f;
    #pragma unroll
    for (int it = 0; it < 3; it++) {
        int gg  = tid + it * 192;
        int row = gg / 12;
        int w0  = (gg - row * 12) << 2;

        float4 q4 = *(const float4*)(qp + row * WD + w0);
        float ql[4] = {q4.x * LOG2E, q4.y * LOG2E, q4.z * LOG2E, q4.w * LOG2E};
        float qb[4][7];
        #pragma unroll
        for (int o = 0; o < 4; o++)
            #pragma unroll
            for (int j = 0; j < 7; j++) qb[o][j] = ql[o] * bias[j];

        float ssum[4] = {0.f, 0.f, 0.f, 0.f};
        float avec[4] = {0.f, 0.f, 0.f, 0.f};

        #pragma unroll
        for (int kh = 0; kh < 7; kh++) {
            const float* kr = &ks[(row + kh) * 56 + w0];
            const float* vr = &vs[(row + kh) * 56 + w0];
            float kvv[12], vvv[12];
            {
                float4 t0 = *(const float4*)(kr);
                float4 t1 = *(const float4*)(kr + 4);
                float4 t2 = *(const float4*)(kr + 8);
                kvv[0]=t0.x; kvv[1]=t0.y; kvv[2]=t0.z; kvv[3]=t0.w;
                kvv[4]=t1.x; kvv[5]=t1.y; kvv[6]=t1.z; kvv[7]=t1.w;
                kvv[8]=t2.x; kvv[9]=t2.y; kvv[10]=t2.z; kvv[11]=t2.w;
                float4 u0 = *(const float4*)(vr);
                float4 u1 = *(const float4*)(vr + 4);
                float4 u2 = *(const float4*)(vr + 8);
                vvv[0]=u0.x; vvv[1]=u0.y; vvv[2]=u0.z; vvv[3]=u0.w;
                vvv[4]=u1.x; vvv[5]=u1.y; vvv[6]=u1.z; vvv[7]=u1.w;
                vvv[8]=u2.x; vvv[9]=u2.y; vvv[10]=u2.z; vvv[11]=u2.w;
            }
            #pragma unroll
            for (int kw = 0; kw < 7; kw++) {
                #pragma unroll
                for (int o = 0; o < 4; o++) {
                    int idx = o + kw + 1;
                    float qbb = USEH ? qb[o][kh] : qb[o][kw];
                    float t = fmaf(ql[o], kvv[idx], qbb);
                    float e;
                    asm("ex2.approx.f32 %0, %1;" : "=f"(e) : "f"(t));
                    ssum[o] += e;
                    avec[o] = fmaf(e, vvv[idx], avec[o]);
                }
            }
        }
        float4 r = make_float4(avec[0] / ssum[0], avec[1] / ssum[1],
                               avec[2] / ssum[2], avec[3] / ssum[3]);
        *(float4*)(op + row * WD + w0) = r;
    }
}

__global__ __launch_bounds__(192) void attn_kernel(
    const float* __restrict__ rel_h, const float* __restrict__ rel_w,
    float* __restrict__ out)
{
    __shared__ float kvbuf[2 * 3024];
    float* ks = kvbuf;
    float* vs = kvbuf + 3024;

    int plane = blockIdx.x;          // 0..511 = b*256 + c
    int c = plane & 255;
    bool useH = (c < 128);

    const float* kp = g_k + (size_t)plane * HW;
    const float* vp = g_v + (size_t)plane * HW;
    const float* qp = g_q + (size_t)plane * HW;
    float*       op = out + (size_t)plane * HW;

    int tid = threadIdx.x;

    for (int i = tid; i < 1512; i += 192)
        ((float4*)kvbuf)[i] = make_float4(0.f, 0.f, 0.f, 0.f);
    __syncthreads();
    for (int i = tid; i < 576; i += 192) {
        int y  = i / 12;
        int x4 = (i - y * 12) << 2;
        int s  = (y + 3) * 56 + x4 + 4;
        *(float4*)(ks + s) = *(const float4*)(kp + y * WD + x4);
        *(float4*)(vs + s) = *(const float4*)(vp + y * WD + x4);
    }
    const float* rb = useH ? (rel_h + c * 7) : (rel_w + (c - 128) * 7);
    float bias[7];
    #pragma unroll
    for (int j = 0; j < 7; j++) bias[j] = rb[j];
    __syncthreads();

    if (useH) attn_compute<true >(ks, vs, qp, op, bias, tid);
    else      attn_compute<false>(ks, vs, qp, op, bias, tid);
}

extern "C" void kernel_launch(void* const* d_in, const int* in_sizes, int n_in,
                              void* d_out, int out_size) {
    const float* x  = (const float*)d_in[0];
    const float* wq = (const float*)d_in[1];
    const float* wk = (const float*)d_in[2];
    const float* wv = (const float*)d_in[3];
    const float* rh = (const float*)d_in[4];
    const float* rw = (const float*)d_in[5];

    cudaFuncSetAttribute(gemm_kernel, cudaFuncAttributeMaxDynamicSharedMemorySize,
                         GEMM_SMEM);

    prep_kernel<<<dim3(72, 8, 3), dim3(32, 32)>>>(x, wq, wk, wv);
    gemm_kernel<<<dim3(36, 6), 256, GEMM_SMEM>>>();
    attn_kernel<<<512, 192>>>(rh, rw, (float*)d_out);
}

// round 5
// speedup vs baseline: 1.1905x; 1.0477x over previous
#include <cuda_runtime.h>
#include <cuda_bf16.h>
#include <cstdint>

#define NB 2
#define NC 256
#define HW 2304   // 48*48
#define WD 48
#define NPIX (NB * HW)   // 4608

// ---------------- device scratch ----------------
__device__ float g_q[NB * NC * HW];
__device__ float g_k[NB * NC * HW];
__device__ float g_v[NB * NC * HW];
__device__ __nv_bfloat16 g_xt_hi[NPIX * 256];
__device__ __nv_bfloat16 g_xt_lo[NPIX * 256];
__device__ __nv_bfloat16 g_w_hi[768 * 256];
__device__ __nv_bfloat16 g_w_lo[768 * 256];

__device__ __forceinline__ uint32_t smem_u32(const void* p) {
    uint32_t a;
    asm("{ .reg .u64 t; cvta.to.shared.u64 t, %1; cvt.u32.u64 %0, t; }"
        : "=r"(a) : "l"(p));
    return a;
}
__device__ __forceinline__ uint32_t pack_bf16(float a, float b) {
    __nv_bfloat162 h = __floats2bfloat162_rn(a, b);
    return *(uint32_t*)&h;
}

// ---------------------------------------------------------------------------
// prep: z<2 -> transpose x [b][c][p] to Xt[P][c] bf16 hi/lo, 32x32 tiles,
//        256 thr, 4 elem/thr, uint2 packed stores.
//        z==2 -> weights [wq;wk;wv] -> bf16 hi/lo, 2 c's per thread (u32).
// grid (72, 8, 3), block 256.
// ---------------------------------------------------------------------------
__global__ __launch_bounds__(256) void prep_kernel(
    const float* __restrict__ x, const float* __restrict__ wq,
    const float* __restrict__ wk, const float* __restrict__ wv)
{
    int tid = threadIdx.x;
    if (blockIdx.z == 2) {
        int gid = (blockIdx.y * 72 + blockIdx.x) * 256 + tid;
        int lin = gid * 2;                 // even c
        if (lin < 768 * 256) {
            int o = lin >> 8;
            int c = lin & 255;
            const float* src = (o < 256) ? (wq + o * 256)
                              : (o < 512) ? (wk + (o - 256) * 256)
                                          : (wv + (o - 512) * 256);
            float2 v = *(const float2*)(src + c);
            __nv_bfloat16 h0 = __float2bfloat16(v.x);
            __nv_bfloat16 h1 = __float2bfloat16(v.y);
            float l0 = v.x - __bfloat162float(h0);
            float l1 = v.y - __bfloat162float(h1);
            ((uint32_t*)g_w_hi)[gid] =
                ((uint32_t)*(uint16_t*)&h1 << 16) | *(uint16_t*)&h0;
            ((uint32_t*)g_w_lo)[gid] = pack_bf16(l0, l1);
        }
        return;
    }
    __shared__ float t[32][33];
    int p0 = blockIdx.x * 32;
    int c0 = blockIdx.y * 32;
    int b  = blockIdx.z;
    #pragma unroll
    for (int k = 0; k < 4; k++) {
        int idx = k * 256 + tid;
        int cl  = idx >> 5;
        int pl  = idx & 31;
        t[cl][pl] = x[(b * 256 + c0 + cl) * HW + p0 + pl];
    }
    __syncthreads();
    int pl   = tid >> 3;          // 0..31
    int col8 = tid & 7;           // 0..7 -> 4 c's each
    int c4   = col8 * 4;
    float v0 = t[c4 + 0][pl], v1 = t[c4 + 1][pl];
    float v2 = t[c4 + 2][pl], v3 = t[c4 + 3][pl];
    __nv_bfloat16 h0 = __float2bfloat16(v0), h1 = __float2bfloat16(v1);
    __nv_bfloat16 h2 = __float2bfloat16(v2), h3 = __float2bfloat16(v3);
    uint2 hi, lo;
    hi.x = ((uint32_t)*(uint16_t*)&h1 << 16) | *(uint16_t*)&h0;
    hi.y = ((uint32_t)*(uint16_t*)&h3 << 16) | *(uint16_t*)&h2;
    lo.x = pack_bf16(v0 - __bfloat162float(h0), v1 - __bfloat162float(h1));
    lo.y = pack_bf16(v2 - __bfloat162float(h2), v3 - __bfloat162float(h3));
    size_t P = (size_t)b * HW + p0 + pl;
    *(uint2*)((char*)g_xt_hi + P * 512 + c0 * 2 + col8 * 8) = hi;
    *(uint2*)((char*)g_xt_lo + P * 512 + c0 * 2 + col8 * 8) = lo;
}

// ---------------------------------------------------------------------------
// GEMM mma.sync m16n8k16 bf16, hi/lo 3-pass. Block 64oc x 128pix, 8 warps
// (2x4), warp tile 32x32, K-tile 64, pitch 72 bf16, 3 CTA/SM.
// grid (36 pix-tiles, 12 oc-tiles) = 432 blocks, 256 threads.
// ---------------------------------------------------------------------------
#define A_TILE_B 9216              // 64 * 144
#define B_TILE_B 18432             // 128 * 144
#define GEMM_SMEM (2 * A_TILE_B + 2 * B_TILE_B)   // 55296

__device__ __forceinline__ void mma_bf16(float* d, const uint32_t* a,
                                         const uint32_t* b) {
    asm volatile(
        "mma.sync.aligned.m16n8k16.row.col.f32.bf16.bf16.f32 "
        "{%0,%1,%2,%3}, {%4,%5,%6,%7}, {%8,%9}, {%0,%1,%2,%3};"
        : "+f"(d[0]), "+f"(d[1]), "+f"(d[2]), "+f"(d[3])
        : "r"(a[0]), "r"(a[1]), "r"(a[2]), "r"(a[3]), "r"(b[0]), "r"(b[1]));
}

__global__ __launch_bounds__(256, 3) void gemm_kernel() {
    extern __shared__ char sm[];
    uint32_t uS = smem_u32(sm);

    int tid = threadIdx.x;
    int l   = tid & 31;
    int wid = tid >> 5;
    int wm  = wid >> 2;      // 0..1, 32 oc each
    int wn  = wid & 3;       // 0..3, 32 pix each

    int N0 = blockIdx.x * 128;
    int M0 = blockIdx.y * 64;

    const char* aw[2] = { (const char*)g_w_hi  + (size_t)M0 * 512,
                          (const char*)g_w_lo  + (size_t)M0 * 512 };
    const char* bx[2] = { (const char*)g_xt_hi + (size_t)N0 * 512,
                          (const char*)g_xt_lo + (size_t)N0 * 512 };

    float acc[2][4][4];
    #pragma unroll
    for (int i = 0; i < 2; i++)
        #pragma unroll
        for (int j = 0; j < 4; j++)
            #pragma unroll
            for (int r = 0; r < 4; r++) acc[i][j][r] = 0.f;

    uint32_t aLane = (uint32_t)((wm * 32 + (l & 15)) * 144 + (l >> 4) * 16);
    uint32_t bLane = (uint32_t)((wn * 32 + ((l >> 4) & 1) * 8 + (l & 7)) * 144
                                + ((l >> 3) & 1) * 16);

    const int selA[3] = {0, 0, 1};
    const int selB[3] = {0, 1, 0};

    for (int kt = 0; kt < 4; kt++) {
        __syncthreads();
        // fill: A 2x(64x8) + B 2x(128x8) = 3072 chunks, 12 iters
        #pragma unroll
        for (int it = 0; it < 12; it++) {
            int lin = it * 256 + tid;
            if (lin < 1024) {
                int tile = lin >> 9;
                int rem  = lin & 511;
                int row  = rem >> 3;
                int ch   = rem & 7;
                uint4 v = *(const uint4*)(aw[tile] + row * 512 + kt * 128 + ch * 16);
                *(uint4*)(sm + tile * A_TILE_B + row * 144 + ch * 16) = v;
            } else {
                int l2   = lin - 1024;
                int tile = l2 >> 10;
                int rem  = l2 & 1023;
                int row  = rem >> 3;
                int ch   = rem & 7;
                uint4 v = *(const uint4*)(bx[tile] + row * 512 + kt * 128 + ch * 16);
                *(uint4*)(sm + 2 * A_TILE_B + tile * B_TILE_B + row * 144 + ch * 16) = v;
            }
        }
        __syncthreads();

        #pragma unroll
        for (int pp = 0; pp < 3; pp++) {
            uint32_t aBase = uS + selA[pp] * A_TILE_B + aLane;
            uint32_t bBase = uS + 2 * A_TILE_B + selB[pp] * B_TILE_B + bLane;
            #pragma unroll
            for (int ks = 0; ks < 4; ks++) {
                uint32_t af[2][4];
                uint32_t bf[4][2];
                #pragma unroll
                for (int i = 0; i < 2; i++) {
                    uint32_t ad = aBase + i * (16 * 144) + ks * 32;
                    asm volatile(
                        "ldmatrix.sync.aligned.m8n8.x4.shared.b16 "
                        "{%0,%1,%2,%3}, [%4];"
                        : "=r"(af[i][0]), "=r"(af[i][1]),
                          "=r"(af[i][2]), "=r"(af[i][3]) : "r"(ad));
                }
                #pragma unroll
                for (int jp = 0; jp < 2; jp++) {
                    uint32_t bd = bBase + jp * (16 * 144) + ks * 32;
                    asm volatile(
                        "ldmatrix.sync.aligned.m8n8.x4.shared.b16 "
                        "{%0,%1,%2,%3}, [%4];"
                        : "=r"(bf[2 * jp][0]), "=r"(bf[2 * jp][1]),
                          "=r"(bf[2 * jp + 1][0]), "=r"(bf[2 * jp + 1][1])
                        : "r"(bd));
                }
                #pragma unroll
                for (int i = 0; i < 2; i++)
                    #pragma unroll
                    for (int j = 0; j < 4; j++)
                        mma_bf16(acc[i][j], af[i], bf[j]);
            }
        }
    }

    int b  = N0 / HW;
    int pl = N0 - b * HW;
    float* obuf = (M0 < 256) ? g_q : (M0 < 512) ? g_k : g_v;
    int ol = M0 & 255;
    int g  = l >> 2;
    int tc = l & 3;
    float* base = obuf + (size_t)b * NC * HW;

    #pragma unroll
    for (int i = 0; i < 2; i++) {
        int oc0 = ol + wm * 32 + i * 16 + g;
        #pragma unroll
        for (int j = 0; j < 4; j++) {
            int pix = pl + wn * 32 + j * 8 + tc * 2;
            *(float2*)(base + (size_t)oc0 * HW + pix) =
                make_float2(acc[i][j][0], acc[i][j][1]);
            *(float2*)(base + (size_t)(oc0 + 8) * HW + pix) =
                make_float2(acc[i][j][2], acc[i][j][3]);
        }
    }
}

// ---------------------------------------------------------------------------
// Attention: one launch, 512 blocks x 192 threads, block-uniform bias mode.
// ---------------------------------------------------------------------------
template <bool USEH>
__device__ __forceinline__ void attn_compute(
    const float* __restrict__ ks, const float* __restrict__ vs,
    const float* __restrict__ qp, float* __restrict__ op,
    const float* bias, int tid)
{
    const float LOG2E = 1.4426950408889634f;
    #pragma unroll
    for (int it = 0; it < 3; it++) {
        int gg  = tid + it * 192;
        int row = gg / 12;
        int w0  = (gg - row * 12) << 2;

        float4 q4 = *(const float4*)(qp + row * WD + w0);
        float ql[4] = {q4.x * LOG2E, q4.y * LOG2E, q4.z * LOG2E, q4.w * LOG2E};
        float qb[4][7];
        #pragma unroll
        for (int o = 0; o < 4; o++)
            #pragma unroll
            for (int j = 0; j < 7; j++) qb[o][j] = ql[o] * bias[j];

        float ssum[4] = {0.f, 0.f, 0.f, 0.f};
        float avec[4] = {0.f, 0.f, 0.f, 0.f};

        #pragma unroll
        for (int kh = 0; kh < 7; kh++) {
            const float* kr = &ks[(row + kh) * 56 + w0];
            const float* vr = &vs[(row + kh) * 56 + w0];
            float kvv[12], vvv[12];
            {
                float4 t0 = *(const float4*)(kr);
                float4 t1 = *(const float4*)(kr + 4);
                float4 t2 = *(const float4*)(kr + 8);
                kvv[0]=t0.x; kvv[1]=t0.y; kvv[2]=t0.z; kvv[3]=t0.w;
                kvv[4]=t1.x; kvv[5]=t1.y; kvv[6]=t1.z; kvv[7]=t1.w;
                kvv[8]=t2.x; kvv[9]=t2.y; kvv[10]=t2.z; kvv[11]=t2.w;
                float4 u0 = *(const float4*)(vr);
                float4 u1 = *(const float4*)(vr + 4);
                float4 u2 = *(const float4*)(vr + 8);
                vvv[0]=u0.x; vvv[1]=u0.y; vvv[2]=u0.z; vvv[3]=u0.w;
                vvv[4]=u1.x; vvv[5]=u1.y; vvv[6]=u1.z; vvv[7]=u1.w;
                vvv[8]=u2.x; vvv[9]=u2.y; vvv[10]=u2.z; vvv[11]=u2.w;
            }
            #pragma unroll
            for (int kw = 0; kw < 7; kw++) {
                #pragma unroll
                for (int o = 0; o < 4; o++) {
                    int idx = o + kw + 1;
                    float qbb = USEH ? qb[o][kh] : qb[o][kw];
                    float t = fmaf(ql[o], kvv[idx], qbb);
                    float e;
                    asm("ex2.approx.f32 %0, %1;" : "=f"(e) : "f"(t));
                    ssum[o] += e;
                    avec[o] = fmaf(e, vvv[idx], avec[o]);
                }
            }
        }
        float4 r = make_float4(avec[0] / ssum[0], avec[1] / ssum[1],
                               avec[2] / ssum[2], avec[3] / ssum[3]);
        *(float4*)(op + row * WD + w0) = r;
    }
}

__global__ __launch_bounds__(192) void attn_kernel(
    const float* __restrict__ rel_h, const float* __restrict__ rel_w,
    float* __restrict__ out)
{
    __shared__ float kvbuf[2 * 3024];
    float* ks = kvbuf;
    float* vs = kvbuf + 3024;

    int plane = blockIdx.x;
    int c = plane & 255;
    bool useH = (c < 128);

    const float* kp = g_k + (size_t)plane * HW;
    const float* vp = g_v + (size_t)plane * HW;
    const float* qp = g_q + (size_t)plane * HW;
    float*       op = out + (size_t)plane * HW;

    int tid = threadIdx.x;

    for (int i = tid; i < 1512; i += 192)
        ((float4*)kvbuf)[i] = make_float4(0.f, 0.f, 0.f, 0.f);
    __syncthreads();
    for (int i = tid; i < 576; i += 192) {
        int y  = i / 12;
        int x4 = (i - y * 12) << 2;
        int s  = (y + 3) * 56 + x4 + 4;
        *(float4*)(ks + s) = *(const float4*)(kp + y * WD + x4);
        *(float4*)(vs + s) = *(const float4*)(vp + y * WD + x4);
    }
    const float* rb = useH ? (rel_h + c * 7) : (rel_w + (c - 128) * 7);
    float bias[7];
    #pragma unroll
    for (int j = 0; j < 7; j++) bias[j] = rb[j];
    __syncthreads();

    if (useH) attn_compute<true >(ks, vs, qp, op, bias, tid);
    else      attn_compute<false>(ks, vs, qp, op, bias, tid);
}

extern "C" void kernel_launch(void* const* d_in, const int* in_sizes, int n_in,
                              void* d_out, int out_size) {
    const float* x  = (const float*)d_in[0];
    const float* wq = (const float*)d_in[1];
    const float* wk = (const float*)d_in[2];
    const float* wv = (const float*)d_in[3];
    const float* rh = (const float*)d_in[4];
    const float* rw = (const float*)d_in[5];

    cudaFuncSetAttribute(gemm_kernel, cudaFuncAttributeMaxDynamicSharedMemorySize,
                         GEMM_SMEM);

    prep_kernel<<<dim3(72, 8, 3), 256>>>(x, wq, wk, wv);
    gemm_kernel<<<dim3(36, 12), 256, GEMM_SMEM>>>();
    attn_kernel<<<512, 192>>>(rh, rw, (float*)d_out);
}